// round 8
// baseline (speedup 1.0000x reference)
#include <cuda_runtime.h>
#include <math_constants.h>

// Pooling_21577915695109: out[b,n,:] = max over m of x_pad[b, index[n,m], :]
// x: (4, 50000, 64) fp32, index: (50000, 16) int32 in [0, 50000]; idx==50000 -> zero row.
//
// R8 shape: MLP-8 gather batches. R7 showed occupancy maxed (8 blocks/SM) but
// issue=38% and L2 stuck at 78% -> request-depth-limited. Front-load 8
// independent gathers per batch (2x int4 index loads first), and route the
// sentinel through a __device__ zero row via pointer-select so every gather is
// an unconditional LDG.128.

constexpr int N_NODES = 50000;
constexpr int M_NEIGH = 16;
constexpr int HID     = 64;

constexpr int THREADS_PER_NODE = 16;   // 16 lanes x float4 = 64 floats = one row
constexpr int NODES_PER_BLOCK  = 16;   // 256 threads / block
constexpr int BLOCK_THREADS    = THREADS_PER_NODE * NODES_PER_BLOCK;

// Zero row for the padding sentinel (static device global: allowed scratch).
__device__ float g_zero_row[HID];   // zero-initialized

__device__ __forceinline__ float4 fmax4(float4 a, float4 b) {
    return make_float4(fmaxf(a.x, b.x), fmaxf(a.y, b.y),
                       fmaxf(a.z, b.z), fmaxf(a.w, b.w));
}

__global__ __launch_bounds__(BLOCK_THREADS, 6)
void pool_max_kernel(const float* __restrict__ x,
                     const int* __restrict__ index,
                     float* __restrict__ out)
{
    const int lane  = threadIdx.x & (THREADS_PER_NODE - 1);
    const int group = threadIdx.x >> 4;
    const int node  = blockIdx.x * NODES_PER_BLOCK + group;   // grid.x*16 == N exactly
    const int batch = blockIdx.y;

    // Row base pre-biased by this lane's column quad: gather = base + idx*64.
    const float* __restrict__ xb   = x + (size_t)batch * (N_NODES * HID) + lane * 4;
    const float* __restrict__ zrow = g_zero_row + lane * 4;

    // This node's 16 neighbor indices as 4 x int4 broadcasts (L1-hit).
    const int4* __restrict__ idx4 = (const int4*)(index + node * M_NEIGH);

    float4 acc = make_float4(-CUDART_INF_F, -CUDART_INF_F, -CUDART_INF_F, -CUDART_INF_F);

    #pragma unroll
    for (int h = 0; h < 2; h++) {
        // 8 indices up front -> 8 independent unconditional gathers in flight.
        const int4 ia = __ldg(idx4 + 2 * h);
        const int4 ib = __ldg(idx4 + 2 * h + 1);
        const int ids[8] = { ia.x, ia.y, ia.z, ia.w, ib.x, ib.y, ib.z, ib.w };

        const float4* p[8];
        #pragma unroll
        for (int j = 0; j < 8; j++) {
            const int idx = ids[j];
            // Unsigned compare: sentinel (and anything unexpected) -> zero row.
            p[j] = ((unsigned)idx < (unsigned)N_NODES)
                       ? (const float4*)(xb + (unsigned)idx * HID)
                       : (const float4*)zrow;
        }

        float4 v[8];
        #pragma unroll
        for (int j = 0; j < 8; j++) v[j] = __ldg(p[j]);

        // Max tree keeps the reduction off the load critical path.
        float4 m0 = fmax4(v[0], v[1]);
        float4 m1 = fmax4(v[2], v[3]);
        float4 m2 = fmax4(v[4], v[5]);
        float4 m3 = fmax4(v[6], v[7]);
        acc = fmax4(acc, fmax4(fmax4(m0, m1), fmax4(m2, m3)));
    }

    const size_t obase = (size_t)batch * (N_NODES * HID)
                       + (unsigned)node * HID + (unsigned)lane * 4;
    *(float4*)(out + obase) = acc;
}

extern "C" void kernel_launch(void* const* d_in, const int* in_sizes, int n_in,
                              void* d_out, int out_size)
{
    const float* x     = (const float*)d_in[0];  // (4, 50000, 64) fp32
    const int*   index = (const int*)d_in[1];    // (50000, 16) int32
    float*       out   = (float*)d_out;          // (4, 50000, 64) fp32

    dim3 grid(N_NODES / NODES_PER_BLOCK, 4);     // 3125 x 4, exact cover
    pool_max_kernel<<<grid, BLOCK_THREADS>>>(x, index, out);
}

// round 9
// speedup vs baseline: 1.0387x; 1.0387x over previous
#include <cuda_runtime.h>
#include <math_constants.h>

// Pooling_21577915695109: out[b,n,:] = max over m of x_pad[b, index[n,m], :]
// x: (4, 50000, 64) fp32, index: (50000, 16) int32 in [0, 50000]; idx==50000 -> zero row.
//
// R9: R7 shape (best occupancy config: 32 regs, 8 blocks/SM) with ONE change —
// gathers use __ldcg (L2-only, no L1 allocation). The gather stream has ~2% L1
// hit rate; skipping L1 allocation removes the miss-fill work that R8 analysis
// identified as saturating the l1tex pipe. Index loads keep __ldg (L1 broadcast).

constexpr int N_NODES = 50000;
constexpr int M_NEIGH = 16;
constexpr int HID     = 64;

constexpr int THREADS_PER_NODE = 16;   // 16 lanes x float4 = 64 floats = one row
constexpr int NODES_PER_BLOCK  = 16;   // 256 threads / block
constexpr int BLOCK_THREADS    = THREADS_PER_NODE * NODES_PER_BLOCK;

__device__ __forceinline__ float4 fmax4(float4 a, float4 b) {
    return make_float4(fmaxf(a.x, b.x), fmaxf(a.y, b.y),
                       fmaxf(a.z, b.z), fmaxf(a.w, b.w));
}

__global__ __launch_bounds__(BLOCK_THREADS, 8)   // pin 32 regs -> 8 blocks/SM
void pool_max_kernel(const float* __restrict__ x,
                     const int* __restrict__ index,
                     float* __restrict__ out)
{
    const int lane  = threadIdx.x & (THREADS_PER_NODE - 1);
    const int group = threadIdx.x >> 4;
    const int node  = blockIdx.x * NODES_PER_BLOCK + group;   // grid.x*16 == N exactly
    const int batch = blockIdx.y;

    // Row pointer pre-biased by this lane's column quad: gather = base + idx*64.
    const float* __restrict__ xb = x + (size_t)batch * (N_NODES * HID) + lane * 4;

    // This node's 16 neighbor indices as 4 x int4 broadcasts (L1-hit, keep __ldg).
    const int4* __restrict__ idx4 = (const int4*)(index + node * M_NEIGH);

    float4 acc = make_float4(-CUDART_INF_F, -CUDART_INF_F, -CUDART_INF_F, -CUDART_INF_F);
    const float4 zero4 = make_float4(0.f, 0.f, 0.f, 0.f);

    #pragma unroll
    for (int c = 0; c < 4; c++) {
        const int4 iv = __ldg(idx4 + c);
        const int ids[4] = { iv.x, iv.y, iv.z, iv.w };

        #pragma unroll
        for (int j = 0; j < 4; j++) {
            const int idx = ids[j];
            // Unsigned compare: the N_NODES sentinel (and anything unexpected)
            // takes the zero-row path -> no OOB possible.
            const bool valid = ((unsigned)idx < (unsigned)N_NODES);
            // L2-only gather: no L1 allocation for a ~0%-L1-hit stream.
            const float4 v = valid ? __ldcg((const float4*)(xb + (unsigned)idx * HID))
                                   : zero4;
            acc = fmax4(acc, v);
        }
    }

    const size_t obase = (size_t)batch * (N_NODES * HID)
                       + (unsigned)node * HID + (unsigned)lane * 4;
    *(float4*)(out + obase) = acc;
}

extern "C" void kernel_launch(void* const* d_in, const int* in_sizes, int n_in,
                              void* d_out, int out_size)
{
    const float* x     = (const float*)d_in[0];  // (4, 50000, 64) fp32
    const int*   index = (const int*)d_in[1];    // (50000, 16) int32
    float*       out   = (float*)d_out;          // (4, 50000, 64) fp32

    dim3 grid(N_NODES / NODES_PER_BLOCK, 4);     // 3125 x 4, exact cover
    pool_max_kernel<<<grid, BLOCK_THREADS>>>(x, index, out);
}